// round 6
// baseline (speedup 1.0000x reference)
#include <cuda_runtime.h>
#include <cuda_fp16.h>

#define BB 4
#define MM 128
#define LL 512
#define DD 768

#define LSPLIT 12
#define LMAX   43
#define APADU  132          // u32 row stride for sh_a (16B-aligned rows)
#define NEGH   0xFC00FC00u  // fp16x2 (-inf,-inf)
#define NDB    (DD / 128)   // 6 d-blocks

// fp16 partials [LSPLIT][B][M][D] = 9.4 MB static scratch (no allocs)
__device__ unsigned short g_scratch[LSPLIT * BB * MM * DD];
// per-(b,dblk) arrival counters, zero-init; last block resets -> replay-safe
__device__ int g_cnt[BB * NDB];

#define SH_H_U32   (LMAX * 64)
#define SMEM_BYTES ((SH_H_U32 + LMAX * APADU) * (int)sizeof(unsigned int))  // ~33.7 KB

__global__ __launch_bounds__(512, 2)
void mr_fused(const float* __restrict__ h, const int* __restrict__ mask,
              float* __restrict__ out)
{
    extern __shared__ unsigned int sm[];
    unsigned int* sh_h = sm;              // [l][64] fp16x2 (128 d)
    unsigned int* sh_a = sm + SH_H_U32;   // [l][APADU] additive splat
    __shared__ int sh_last;

    const int b    = blockIdx.z;
    const int dblk = blockIdx.x;
    const int d0   = dblk * 128;
    const int sp   = blockIdx.y;
    const int l0   = sp * 42 + (sp < 8 ? sp : 8);   // 8x43 + 4x42 = 512
    const int llen = 42 + (sp < 8 ? 1 : 0);

    const int tid  = threadIdx.x;
    const int lane = tid & 31;
    const int w    = tid >> 5;            // 16 warps; warp w -> m rows [8w, 8w+8)

    // ---- stage h tile: coalesced float4 LDG -> fp16x2 -> STS ----
    {
        const float4* hg = (const float4*)h + ((size_t)b * LL + l0) * (DD / 4) + (d0 >> 2);
        const int n = llen * 32;
        for (int idx = tid; idx < n; idx += 512) {
            const int l = idx >> 5, q = idx & 31;
            const float4 v = hg[(size_t)l * (DD / 4) + q];
            const half2 p0 = __float22half2_rn(make_float2(v.x, v.y));
            const half2 p1 = __float22half2_rn(make_float2(v.z, v.w));
            sh_h[l * 64 + q * 2]     = *(const unsigned int*)&p0;
            sh_h[l * 64 + q * 2 + 1] = *(const unsigned int*)&p1;
        }
    }
    // ---- stage mask transposed [l][m]; LDG coalesced over l ----
    for (int m = w; m < MM; m += 16) {
        const int* mg = mask + ((size_t)b * MM + m) * LL + l0;
        for (int lb = lane; lb < llen; lb += 32)
            sh_a[lb * APADU + m] = mg[lb] ? 0u : NEGH;
    }
    __syncthreads();

    // ---- accumulate: 8 m x 128 d (fp16x2) per warp ----
    const unsigned int ninf = NEGH;
    const half2 hninf = *(const half2*)&ninf;
    half2 acc[8][2];
#pragma unroll
    for (int i = 0; i < 8; ++i) { acc[i][0] = hninf; acc[i][1] = hninf; }

    const int mb = w * 8;
#pragma unroll 2
    for (int l = 0; l < llen; ++l) {
        const uint2 hv = *(const uint2*)&sh_h[l * 64 + lane * 2];
        const half2 h0 = *(const half2*)&hv.x;
        const half2 h1 = *(const half2*)&hv.y;
        const uint4 a0 = *(const uint4*)&sh_a[l * APADU + mb];      // uniform -> broadcast
        const uint4 a1 = *(const uint4*)&sh_a[l * APADU + mb + 4];
        unsigned int av[8] = {a0.x, a0.y, a0.z, a0.w, a1.x, a1.y, a1.z, a1.w};
#pragma unroll
        for (int i = 0; i < 8; ++i) {
            const half2 a = *(const half2*)&av[i];
            acc[i][0] = __hmax2(acc[i][0], __hadd2(h0, a));
            acc[i][1] = __hmax2(acc[i][1], __hadd2(h1, a));
        }
    }

    // ---- write fp16 partials [sp][b][m][d] ----
    unsigned short* op = g_scratch + (((size_t)sp * BB + b) * MM + mb) * DD + d0 + lane * 4;
#pragma unroll
    for (int i = 0; i < 8; ++i) {
        uint2 o;
        o.x = *(const unsigned int*)&acc[i][0];
        o.y = *(const unsigned int*)&acc[i][1];
        *(uint2*)(op + (size_t)i * DD) = o;
    }

    // ---- last-block combine for this (b, dblk) group ----
    __threadfence();
    __syncthreads();
    if (tid == 0) {
        const int old = atomicAdd(&g_cnt[b * NDB + dblk], 1);
        sh_last = (old == LSPLIT - 1) ? 1 : 0;
    }
    __syncthreads();
    if (!sh_last) return;
    if (tid == 0) g_cnt[b * NDB + dblk] = 0;   // reset for next launch
    __threadfence();                            // acquire side

    // tile = 128 m x 128 d = 4096 uint2 (4 fp16 each); 8 per thread
    const uint2* s = (const uint2*)g_scratch;
    const size_t spStride = (size_t)BB * MM * DD / 4;   // uint2 units
#pragma unroll
    for (int k = 0; k < 8; ++k) {
        const int e = k * 512 + tid;          // 0..4095
        const int m = e >> 5, q = e & 31;     // 32 uint2 per m-row (128 d)
        const size_t base = (((size_t)b * MM + m) * DD + d0) / 4 + q;

        uint2 v[LSPLIT];
#pragma unroll
        for (int p = 0; p < LSPLIT; ++p)      // MLP 12
            v[p] = s[p * spStride + base];

        half2 r0 = *(const half2*)&v[0].x;
        half2 r1 = *(const half2*)&v[0].y;
#pragma unroll
        for (int p = 1; p < LSPLIT; ++p) {
            r0 = __hmax2(r0, *(const half2*)&v[p].x);
            r1 = __hmax2(r1, *(const half2*)&v[p].y);
        }
        const float2 f0 = __half22float2(r0);
        const float2 f1 = __half22float2(r1);
        float4 o; o.x = f0.x; o.y = f0.y; o.z = f1.x; o.w = f1.y;
        ((float4*)out)[base] = o;             // same index math, float4 units
    }
}

extern "C" void kernel_launch(void* const* d_in, const int* in_sizes, int n_in,
                              void* d_out, int out_size)
{
    const float* h    = (const float*)d_in[0];
    const int*   mask = (const int*)  d_in[1];
    float*       out  = (float*)d_out;

    cudaFuncSetAttribute(mr_fused,
                         cudaFuncAttributeMaxDynamicSharedMemorySize, SMEM_BYTES);

    dim3 grid(NDB, LSPLIT, BB);   // 6 x 12 x 4 = 288 blocks, occ 2
    mr_fused<<<grid, 512, SMEM_BYTES>>>(h, mask, out);
}

// round 7
// speedup vs baseline: 1.1115x; 1.1115x over previous
#include <cuda_runtime.h>
#include <cuda_fp16.h>

#define BB 4
#define MM 128
#define LL 512
#define DD 768

#define LSPLIT 8
#define LMAX   64
#define APADU  132          // u32 row stride for sh_a (16B-aligned rows)
#define NEGH   0xFC00FC00u  // fp16x2 (-inf,-inf)

// fp16 partials [LSPLIT][B][M][D] = 6.3 MB static scratch (no allocs)
__device__ unsigned short g_scratch[LSPLIT * BB * MM * DD];

#define SH_H_U32   (LMAX * 64)
#define SMEM_BYTES ((SH_H_U32 + LMAX * APADU) * (int)sizeof(unsigned int))  // ~50.2 KB

__global__ __launch_bounds__(512, 2)
void mr_main(const float* __restrict__ h, const int* __restrict__ mask)
{
    extern __shared__ unsigned int sm[];
    unsigned int* sh_h = sm;              // [l][64] fp16x2 (128 d)
    unsigned int* sh_a = sm + SH_H_U32;   // [l][APADU] additive splat (0 or -inf,-inf)

    const int b    = blockIdx.z;
    const int d0   = blockIdx.x * 128;
    const int sp   = blockIdx.y;
    const int l0   = sp * LMAX;           // exact split: 8 x 64 = 512

    const int tid  = threadIdx.x;
    const int lane = tid & 31;
    const int w    = tid >> 5;            // 16 warps; warp w -> m rows [8w, 8w+8)

    // ---- stage h tile: coalesced float4 LDG -> fp16x2 -> STS (4 full iters) ----
    {
        const float4* hg = (const float4*)h + ((size_t)b * LL + l0) * (DD / 4) + (d0 >> 2);
#pragma unroll
        for (int it = 0; it < (LMAX * 32) / 512; ++it) {
            const int idx = it * 512 + tid;
            const int l = idx >> 5, q = idx & 31;
            const float4 v = hg[(size_t)l * (DD / 4) + q];
            const half2 p0 = __float22half2_rn(make_float2(v.x, v.y));
            const half2 p1 = __float22half2_rn(make_float2(v.z, v.w));
            sh_h[l * 64 + q * 2]     = *(const unsigned int*)&p0;
            sh_h[l * 64 + q * 2 + 1] = *(const unsigned int*)&p1;
        }
    }
    // ---- stage mask transposed [l][m]; LDG coalesced over l (2 full iters) ----
#pragma unroll
    for (int mi = 0; mi < MM / 16; ++mi) {
        const int m = w + mi * 16;
        const int* mg = mask + ((size_t)b * MM + m) * LL + l0;
#pragma unroll
        for (int li = 0; li < LMAX / 32; ++li) {
            const int lb = lane + li * 32;
            sh_a[lb * APADU + m] = mg[lb] ? 0u : NEGH;
        }
    }
    __syncthreads();

    // ---- accumulate: 8 m x 128 d (fp16x2) per warp ----
    const unsigned int ninf = NEGH;
    const half2 hninf = *(const half2*)&ninf;
    half2 acc[8][2];
#pragma unroll
    for (int i = 0; i < 8; ++i) { acc[i][0] = hninf; acc[i][1] = hninf; }

    const int mb = w * 8;
#pragma unroll 2
    for (int l = 0; l < LMAX; ++l) {
        const uint2 hv = *(const uint2*)&sh_h[l * 64 + lane * 2];
        const half2 h0 = *(const half2*)&hv.x;
        const half2 h1 = *(const half2*)&hv.y;
        const uint4 a0 = *(const uint4*)&sh_a[l * APADU + mb];      // uniform -> broadcast
        const uint4 a1 = *(const uint4*)&sh_a[l * APADU + mb + 4];
        unsigned int av[8] = {a0.x, a0.y, a0.z, a0.w, a1.x, a1.y, a1.z, a1.w};
#pragma unroll
        for (int i = 0; i < 8; ++i) {
            const half2 a = *(const half2*)&av[i];
            acc[i][0] = __hmax2(acc[i][0], __hadd2(h0, a));
            acc[i][1] = __hmax2(acc[i][1], __hadd2(h1, a));
        }
    }

    // ---- write fp16 partials [sp][b][m][d], coalesced 8B/thread ----
    unsigned short* op = g_scratch + (((size_t)sp * BB + b) * MM + mb) * DD + d0 + lane * 4;
#pragma unroll
    for (int i = 0; i < 8; ++i) {
        uint2 o;
        o.x = *(const unsigned int*)&acc[i][0];
        o.y = *(const unsigned int*)&acc[i][1];
        *(uint2*)(op + (size_t)i * DD) = o;
    }
}

#define TOTU2 (BB * MM * DD / 4)    // 98304 uint2 (4 fp16 each)

__global__ __launch_bounds__(512, 1)
void mr_combine(float* __restrict__ out)
{
    const int t = blockIdx.x * 512 + threadIdx.x;    // 0..98303
    const uint2* s = (const uint2*)g_scratch;

    uint2 v[LSPLIT];
#pragma unroll
    for (int sp = 0; sp < LSPLIT; ++sp)              // MLP 8
        v[sp] = s[(size_t)sp * TOTU2 + t];

    half2 r0 = *(const half2*)&v[0].x;
    half2 r1 = *(const half2*)&v[0].y;
#pragma unroll
    for (int sp = 1; sp < LSPLIT; ++sp) {
        r0 = __hmax2(r0, *(const half2*)&v[sp].x);
        r1 = __hmax2(r1, *(const half2*)&v[sp].y);
    }
    const float2 f0 = __half22float2(r0);
    const float2 f1 = __half22float2(r1);
    float4 o; o.x = f0.x; o.y = f0.y; o.z = f1.x; o.w = f1.y;
    ((float4*)out)[t] = o;
}

extern "C" void kernel_launch(void* const* d_in, const int* in_sizes, int n_in,
                              void* d_out, int out_size)
{
    const float* h    = (const float*)d_in[0];
    const int*   mask = (const int*)  d_in[1];
    float*       out  = (float*)d_out;

    cudaFuncSetAttribute(mr_main,
                         cudaFuncAttributeMaxDynamicSharedMemorySize, SMEM_BYTES);

    dim3 grid(DD / 128, LSPLIT, BB);      // 6 x 8 x 4 = 192 blocks, occ 2
    mr_main<<<grid, 512, SMEM_BYTES>>>(h, mask);
    mr_combine<<<TOTU2 / 512, 512>>>(out);   // 192 blocks
}